// round 16
// baseline (speedup 1.0000x reference)
#include <cuda_runtime.h>
#include <cuda_fp16.h>
#include <cstdint>

#define N_USERS 100000
#define N_ITEMS 50000
#define N_NODES 150000
#define D 64
#define DH2 32             // D/2 half2 per node row (128B)
#define DU2 16             // D/4 uint2 per node row (128B)
#define DF2 32             // D/2 float2 per node row (256B)
#define NNZ 4800000
#define PAD 96             // slots per row; P(deg>=96) ~ 1e-18 for Poisson(32)
                           // 150K*96*8B = 115.2MB -> colvPad now fits in L2

// ---------------- device-global scratch (no allocations allowed) -----------
// Device globals are zero-initialized; colvPad slots beyond each row's degree
// are never written -> {col_off=0, val=0.0f} -> v*x contributes 0 (harmless).
__device__ uint2 g_egoH[N_NODES * DU2];        // 19.2 MB fp16 ego
__device__ uint2 g_bufA[N_NODES * DU2];        // 19.2 MB hop-1 out (fp16)
__device__ uint2 g_bufB[N_NODES * DU2];        // 19.2 MB hop-2 out (fp16)
__device__ int2  g_colvPad[N_NODES * PAD + 32];// 115.2 MB padded CSR slots
__device__ int   g_cnt[N_NODES];               // per-row fill counters == degree

// ---------------------------------------------------------------------------
// Fused build kernel: all threads convert one float2 of ego to fp16; the
// first NNZ/4 threads also scatter 4 COO edges into the padded CSR. The
// convert hides in the scatter's atomic/store latency shadow.
// Column indices are stored PRE-SCALED by DU2 (uint2 row offset) so the hop
// kernels need only one LEA per gather address.
// ---------------------------------------------------------------------------
__global__ void __launch_bounds__(256) build_kernel(
    const float2* __restrict__ u, const float2* __restrict__ it,
    __half2* __restrict__ egoH,
    const int4* __restrict__ row4, const int4* __restrict__ col4,
    const float4* __restrict__ vals4)
{
    int i = blockIdx.x * blockDim.x + threadIdx.x;

    // ---- convert slice ----
    const int total = N_NODES * DH2;
    const int nu = N_USERS * DF2;
    if (i < total) {
        float2 v = (i < nu) ? __ldcs(u + i) : __ldcs(it + (i - nu));
        egoH[i] = __float22half2_rn(v);
    }

    // ---- scatter slice ----
    if (i < NNZ / 4) {
        int4   r = __ldcs(row4 + i);
        int4   c = __ldcs(col4 + i);
        float4 v = __ldcs(vals4 + i);
        int p0 = min(atomicAdd(&g_cnt[r.x], 1), PAD - 1);
        int p1 = min(atomicAdd(&g_cnt[r.y], 1), PAD - 1);
        int p2 = min(atomicAdd(&g_cnt[r.z], 1), PAD - 1);
        int p3 = min(atomicAdd(&g_cnt[r.w], 1), PAD - 1);
        __stcs(&g_colvPad[(size_t)r.x * PAD + p0],
               make_int2(c.x * DU2, __float_as_int(v.x)));
        __stcs(&g_colvPad[(size_t)r.y * PAD + p1],
               make_int2(c.y * DU2, __float_as_int(v.y)));
        __stcs(&g_colvPad[(size_t)r.z * PAD + p2],
               make_int2(c.z * DU2, __float_as_int(v.z)));
        __stcs(&g_colvPad[(size_t)r.w * PAD + p3],
               make_int2(c.w * DU2, __float_as_int(v.w)));
    }
}

// ---------------------------------------------------------------------------
// Gather SpMM hop — proven R10/R14 structure (regs=32, occ=83%):
// 2 rows/warp, 16 lanes/row, lane owns uint2 (4 dims, 8B); 16-edge metadata
// chunks (128B coalesced) software-pipelined via shfl broadcast; stored col
// offsets are pre-scaled, so gather addr = xh + (cx_off + sub).
// MODE 1: x=egoH; yh=bufA, out_layer = y1
// MODE 2: x=bufA; yh=bufB
// MODE 3: x=bufB; out_all = (bufA + bufB + y3)/3
// ---------------------------------------------------------------------------
template<int MODE>
__global__ void __launch_bounds__(256) hop_kernel(
    const uint2* __restrict__ xh, uint2* __restrict__ yh,
    const uint2* __restrict__ y1h, const uint2* __restrict__ y2h,
    float2* __restrict__ out_all, float2* __restrict__ out_layer)
{
    int gwarp = (blockIdx.x * blockDim.x + threadIdx.x) >> 5;
    int lane  = threadIdx.x & 31;
    int half  = lane >> 4;
    int sub   = lane & 15;
    int row   = gwarp * 2 + half;
    if (row >= N_NODES) return;

    const unsigned mask = 0xFFFFu << (half << 4);
    int beg = row * PAD;
    int deg = min(g_cnt[row], PAD);
    int nfull = deg >> 4;

    float a0 = 0.f, a1 = 0.f, a2 = 0.f, a3 = 0.f;

    // prime chunk 0 (unconditional: pad slots are zeros)
    int2 cv = __ldcs(&g_colvPad[beg + sub]);
    int base = beg;

    for (int c = 0; c < nfull; c++) {
        int2 cur = cv;
        cv = __ldcs(&g_colvPad[base + 16 + sub]);          // unconditional prefetch
        #pragma unroll
        for (int j = 0; j < 16; j++) {
            int cx = __shfl_sync(mask, cur.x, j, 16);      // pre-scaled offset
            int vb = __shfl_sync(mask, cur.y, j, 16);
            uint2 h = __ldg(xh + cx + sub);
            float v = __int_as_float(vb);
            float2 f0 = __half22float2(*reinterpret_cast<__half2*>(&h.x));
            float2 f1 = __half22float2(*reinterpret_cast<__half2*>(&h.y));
            a0 = fmaf(v, f0.x, a0);
            a1 = fmaf(v, f0.y, a1);
            a2 = fmaf(v, f1.x, a2);
            a3 = fmaf(v, f1.y, a3);
        }
        base += 16;
    }

    int rem = deg - (nfull << 4);
    #pragma unroll
    for (int j = 0; j < 16; j++) {
        if (j < rem) {
            int cx = __shfl_sync(mask, cv.x, j, 16);
            int vb = __shfl_sync(mask, cv.y, j, 16);
            uint2 h = __ldg(xh + cx + sub);
            float v = __int_as_float(vb);
            float2 f0 = __half22float2(*reinterpret_cast<__half2*>(&h.x));
            float2 f1 = __half22float2(*reinterpret_cast<__half2*>(&h.y));
            a0 = fmaf(v, f0.x, a0);
            a1 = fmaf(v, f0.y, a1);
            a2 = fmaf(v, f1.x, a2);
            a3 = fmaf(v, f1.y, a3);
        }
    }

    size_t oh = (size_t)row * DU2 + sub;          // fp16 buffer slot
    size_t of = (size_t)row * DF2 + sub * 2;      // fp32 float2 slot (x2)

    if (MODE == 1 || MODE == 2) {
        __half2 p0 = __floats2half2_rn(a0, a1);
        __half2 p1 = __floats2half2_rn(a2, a3);
        uint2 packed;
        packed.x = *reinterpret_cast<unsigned*>(&p0);
        packed.y = *reinterpret_cast<unsigned*>(&p1);
        __stcs(&yh[oh], packed);
    }
    if (MODE == 1) {
        __stcs(&out_layer[of],     make_float2(a0, a1));
        __stcs(&out_layer[of + 1], make_float2(a2, a3));
    }
    if (MODE == 3) {
        const float s = 1.0f / 3.0f;
        uint2 u1 = __ldcs(y1h + oh);
        uint2 u2 = __ldcs(y2h + oh);
        float2 b10 = __half22float2(*reinterpret_cast<__half2*>(&u1.x));
        float2 b11 = __half22float2(*reinterpret_cast<__half2*>(&u1.y));
        float2 b20 = __half22float2(*reinterpret_cast<__half2*>(&u2.x));
        float2 b21 = __half22float2(*reinterpret_cast<__half2*>(&u2.y));
        __stcs(&out_all[of],
               make_float2((b10.x + b20.x + a0) * s, (b10.y + b20.y + a1) * s));
        __stcs(&out_all[of + 1],
               make_float2((b11.x + b21.x + a2) * s, (b11.y + b21.y + a3) * s));
    }
}

// ---------------------------------------------------------------------------
extern "C" void kernel_launch(void* const* d_in, const int* in_sizes, int n_in,
                              void* d_out, int out_size)
{
    const float2* user_e = (const float2*)d_in[0];
    const float2* item_e = (const float2*)d_in[1];
    const int*    row    = (const int*)d_in[2];
    const int*    col    = (const int*)d_in[3];
    const float*  vals   = (const float*)d_in[4];

    float2* out_all   = (float2*)d_out;
    float2* out_layer = out_all + (size_t)N_NODES * DF2;

    void* cntAddr;
    cudaGetSymbolAddress(&cntAddr, g_cnt);
    uint2 *egoH, *bufA, *bufB;
    cudaGetSymbolAddress((void**)&egoH, g_egoH);
    cudaGetSymbolAddress((void**)&bufA, g_bufA);
    cudaGetSymbolAddress((void**)&bufB, g_bufB);

    const int elemBlocks = (N_NODES * DH2 + 255) / 256;   // 18750 (covers scatter's 4688)
    const int hopWarps   = (N_NODES + 1) / 2;             // 2 rows per warp
    const int hopBlocks  = (hopWarps * 32 + 255) / 256;

    // ---- fused fp16-ego convert + one-pass padded CSR build ----
    cudaMemsetAsync(cntAddr, 0, N_NODES * sizeof(int));
    build_kernel<<<elemBlocks, 256>>>(user_e, item_e, (__half2*)egoH,
                                      (const int4*)row, (const int4*)col,
                                      (const float4*)vals);

    // ---- 3 hops; mean deferred to hop 3 ----
    hop_kernel<1><<<hopBlocks, 256>>>(egoH, bufA, nullptr, nullptr,
                                      out_all, out_layer);
    hop_kernel<2><<<hopBlocks, 256>>>(bufA, bufB, nullptr, nullptr,
                                      out_all, out_layer);
    hop_kernel<3><<<hopBlocks, 256>>>(bufB, nullptr, bufA, bufB,
                                      out_all, out_layer);
}

// round 17
// speedup vs baseline: 1.0396x; 1.0396x over previous
#include <cuda_runtime.h>
#include <cuda_fp16.h>
#include <cstdint>

#define N_USERS 100000
#define N_ITEMS 50000
#define N_NODES 150000
#define D 64
#define DH2 32             // D/2 half2 per node row (128B)
#define DU2 16             // D/4 uint2 per node row (128B)
#define DF2 32             // D/2 float2 per node row (256B)
#define NNZ 4800000
#define PAD 128            // slots per row (Poisson(32) max deg << 128)
#define PAD_SHIFT 7

// ---------------- device-global scratch (no allocations allowed) -----------
// Device globals are zero-initialized; colvPad slots beyond each row's degree
// are never written -> {col=0, val=0.0f} -> v*x contributes 0 (harmless).
__device__ uint2 g_egoH[N_NODES * DU2];        // 19.2 MB fp16 ego
__device__ uint2 g_bufA[N_NODES * DU2];        // 19.2 MB hop-1 out (fp16)
__device__ uint2 g_bufB[N_NODES * DU2];        // 19.2 MB hop-2 out (fp16)
__device__ int2  g_colvPad[N_NODES * PAD + 32];// 153.6 MB padded CSR slots
__device__ int   g_cnt[N_NODES];               // per-row fill counters == degree

// ---------------------------------------------------------------------------
// Fused build kernel: all threads convert one float2 of ego to fp16.
// Scatter work is distributed UNIFORMLY: every 4th thread handles one int4
// edge group (lanes 0,4,..,28 -> 8 consecutive int4 = 128B/warp, coalesced),
// so every block carries an equal share of the atomic/store latency instead
// of the first quarter of the grid doing all of it.
// ---------------------------------------------------------------------------
__global__ void __launch_bounds__(256) build_kernel(
    const float2* __restrict__ u, const float2* __restrict__ it,
    __half2* __restrict__ egoH,
    const int4* __restrict__ row4, const int4* __restrict__ col4,
    const float4* __restrict__ vals4)
{
    int i = blockIdx.x * blockDim.x + threadIdx.x;

    // ---- convert slice (all threads) ----
    const int total = N_NODES * DH2;
    const int nu = N_USERS * DF2;
    if (i < total) {
        float2 v = (i < nu) ? __ldcs(u + i) : __ldcs(it + (i - nu));
        egoH[i] = __float22half2_rn(v);
    }

    // ---- scatter slice (every 4th thread, uniformly spread) ----
    if ((i & 3) == 0) {
        int j = i >> 2;                            // edge group index
        if (j < NNZ / 4) {
            int4   r = __ldcs(row4 + j);
            int4   c = __ldcs(col4 + j);
            float4 v = __ldcs(vals4 + j);
            int p0 = atomicAdd(&g_cnt[r.x], 1) & (PAD - 1);
            int p1 = atomicAdd(&g_cnt[r.y], 1) & (PAD - 1);
            int p2 = atomicAdd(&g_cnt[r.z], 1) & (PAD - 1);
            int p3 = atomicAdd(&g_cnt[r.w], 1) & (PAD - 1);
            __stcs(&g_colvPad[((size_t)r.x << PAD_SHIFT) + p0],
                   make_int2(c.x, __float_as_int(v.x)));
            __stcs(&g_colvPad[((size_t)r.y << PAD_SHIFT) + p1],
                   make_int2(c.y, __float_as_int(v.y)));
            __stcs(&g_colvPad[((size_t)r.z << PAD_SHIFT) + p2],
                   make_int2(c.z, __float_as_int(v.z)));
            __stcs(&g_colvPad[((size_t)r.w << PAD_SHIFT) + p3],
                   make_int2(c.w, __float_as_int(v.w)));
        }
    }
}

// ---------------------------------------------------------------------------
// Gather SpMM hop — EXACT R14 structure (proven 295.0us total; regs=32,
// occ=83%): 2 rows/warp, 16 lanes/row, lane owns uint2 (4 dims, 8B); 16-edge
// metadata chunks (128B coalesced) software-pipelined via shfl broadcast;
// unconditional prime/prefetch (pad slots guaranteed zero).
// MODE 1: x=egoH; yh=bufA, out_layer = y1
// MODE 2: x=bufA; yh=bufB
// MODE 3: x=bufB; out_all = (bufA + bufB + y3)/3
// ---------------------------------------------------------------------------
template<int MODE>
__global__ void __launch_bounds__(256) hop_kernel(
    const uint2* __restrict__ xh, uint2* __restrict__ yh,
    const uint2* __restrict__ y1h, const uint2* __restrict__ y2h,
    float2* __restrict__ out_all, float2* __restrict__ out_layer)
{
    int gwarp = (blockIdx.x * blockDim.x + threadIdx.x) >> 5;
    int lane  = threadIdx.x & 31;
    int half  = lane >> 4;
    int sub   = lane & 15;
    int row   = gwarp * 2 + half;
    if (row >= N_NODES) return;

    const unsigned mask = 0xFFFFu << (half << 4);
    int beg = row << PAD_SHIFT;
    int deg = min(g_cnt[row], PAD);
    int nfull = deg >> 4;

    float a0 = 0.f, a1 = 0.f, a2 = 0.f, a3 = 0.f;

    // prime chunk 0 (unconditional: pad slots are zeros)
    int2 cv = __ldcs(&g_colvPad[beg + sub]);
    int base = beg;

    for (int c = 0; c < nfull; c++) {
        int2 cur = cv;
        cv = __ldcs(&g_colvPad[base + 16 + sub]);          // unconditional prefetch
        #pragma unroll
        for (int j = 0; j < 16; j++) {
            int cx = __shfl_sync(mask, cur.x, j, 16);
            int vb = __shfl_sync(mask, cur.y, j, 16);
            uint2 h = __ldg(xh + (size_t)cx * DU2 + sub);
            float v = __int_as_float(vb);
            float2 f0 = __half22float2(*reinterpret_cast<__half2*>(&h.x));
            float2 f1 = __half22float2(*reinterpret_cast<__half2*>(&h.y));
            a0 = fmaf(v, f0.x, a0);
            a1 = fmaf(v, f0.y, a1);
            a2 = fmaf(v, f1.x, a2);
            a3 = fmaf(v, f1.y, a3);
        }
        base += 16;
    }

    int rem = deg - (nfull << 4);
    #pragma unroll
    for (int j = 0; j < 16; j++) {
        if (j < rem) {
            int cx = __shfl_sync(mask, cv.x, j, 16);
            int vb = __shfl_sync(mask, cv.y, j, 16);
            uint2 h = __ldg(xh + (size_t)cx * DU2 + sub);
            float v = __int_as_float(vb);
            float2 f0 = __half22float2(*reinterpret_cast<__half2*>(&h.x));
            float2 f1 = __half22float2(*reinterpret_cast<__half2*>(&h.y));
            a0 = fmaf(v, f0.x, a0);
            a1 = fmaf(v, f0.y, a1);
            a2 = fmaf(v, f1.x, a2);
            a3 = fmaf(v, f1.y, a3);
        }
    }

    size_t oh = (size_t)row * DU2 + sub;          // fp16 buffer slot
    size_t of = (size_t)row * DF2 + sub * 2;      // fp32 float2 slot (x2)

    if (MODE == 1 || MODE == 2) {
        __half2 p0 = __floats2half2_rn(a0, a1);
        __half2 p1 = __floats2half2_rn(a2, a3);
        uint2 packed;
        packed.x = *reinterpret_cast<unsigned*>(&p0);
        packed.y = *reinterpret_cast<unsigned*>(&p1);
        __stcs(&yh[oh], packed);
    }
    if (MODE == 1) {
        __stcs(&out_layer[of],     make_float2(a0, a1));
        __stcs(&out_layer[of + 1], make_float2(a2, a3));
    }
    if (MODE == 3) {
        const float s = 1.0f / 3.0f;
        uint2 u1 = __ldcs(y1h + oh);
        uint2 u2 = __ldcs(y2h + oh);
        float2 b10 = __half22float2(*reinterpret_cast<__half2*>(&u1.x));
        float2 b11 = __half22float2(*reinterpret_cast<__half2*>(&u1.y));
        float2 b20 = __half22float2(*reinterpret_cast<__half2*>(&u2.x));
        float2 b21 = __half22float2(*reinterpret_cast<__half2*>(&u2.y));
        __stcs(&out_all[of],
               make_float2((b10.x + b20.x + a0) * s, (b10.y + b20.y + a1) * s));
        __stcs(&out_all[of + 1],
               make_float2((b11.x + b21.x + a2) * s, (b11.y + b21.y + a3) * s));
    }
}

// ---------------------------------------------------------------------------
extern "C" void kernel_launch(void* const* d_in, const int* in_sizes, int n_in,
                              void* d_out, int out_size)
{
    const float2* user_e = (const float2*)d_in[0];
    const float2* item_e = (const float2*)d_in[1];
    const int*    row    = (const int*)d_in[2];
    const int*    col    = (const int*)d_in[3];
    const float*  vals   = (const float*)d_in[4];

    float2* out_all   = (float2*)d_out;
    float2* out_layer = out_all + (size_t)N_NODES * DF2;

    void* cntAddr;
    cudaGetSymbolAddress(&cntAddr, g_cnt);
    uint2 *egoH, *bufA, *bufB;
    cudaGetSymbolAddress((void**)&egoH, g_egoH);
    cudaGetSymbolAddress((void**)&bufA, g_bufA);
    cudaGetSymbolAddress((void**)&bufB, g_bufB);

    const int elemBlocks = (N_NODES * DH2 + 255) / 256;   // 18750
    const int hopWarps   = (N_NODES + 1) / 2;             // 2 rows per warp
    const int hopBlocks  = (hopWarps * 32 + 255) / 256;

    // ---- fused fp16-ego convert + one-pass padded CSR build ----
    cudaMemsetAsync(cntAddr, 0, N_NODES * sizeof(int));
    build_kernel<<<elemBlocks, 256>>>(user_e, item_e, (__half2*)egoH,
                                      (const int4*)row, (const int4*)col,
                                      (const float4*)vals);

    // ---- 3 hops; mean deferred to hop 3 ----
    hop_kernel<1><<<hopBlocks, 256>>>(egoH, bufA, nullptr, nullptr,
                                      out_all, out_layer);
    hop_kernel<2><<<hopBlocks, 256>>>(bufA, bufB, nullptr, nullptr,
                                      out_all, out_layer);
    hop_kernel<3><<<hopBlocks, 256>>>(bufB, nullptr, bufA, bufB,
                                      out_all, out_layer);
}